// round 17
// baseline (speedup 1.0000x reference)
#include <cuda_runtime.h>
#include <cuda_fp16.h>
#include <math.h>
#include <stdint.h>

#define BB   4
#define LL   1024
#define MM   (BB*LL)        // 4096 tokens
#define DIMS 4096
#define NH   32
#define NKV  8
#define HD   128
#define DKV  (NKV*HD)       // 1024

// Scratch (no cudaMalloc allowed) ------------------------------------------
__device__ __half g_xh [(size_t)MM*DIMS];
__device__ __half g_wqh[(size_t)DIMS*DIMS];
__device__ __half g_wkh[(size_t)DKV*DIMS];
__device__ __half g_wvh[(size_t)DKV*DIMS];
__device__ __half g_ah [(size_t)MM*DIMS];   // attention out (half, feeds wo GEMM)
// pre-split hi/lo fp16 Q/K/V, head-major layout [b][head][seq][d]
__device__ __half g_qhi[(size_t)MM*DIMS];
__device__ __half g_qlo[(size_t)MM*DIMS];
__device__ __half g_khi[(size_t)MM*DKV];
__device__ __half g_klo[(size_t)MM*DKV];
__device__ __half g_vhi[(size_t)MM*DKV];
__device__ __half g_vlo[(size_t)MM*DKV];

// ======================= helpers ===========================================
__device__ __forceinline__ uint32_t smem_u32(const void* p) {
    uint32_t a;
    asm("{ .reg .u64 t; cvta.to.shared.u64 t, %1; cvt.u32.u64 %0, t; }"
        : "=r"(a) : "l"(p));
    return a;
}
__device__ __forceinline__ void ldx4(uint32_t* r, uint32_t addr) {
    asm volatile("ldmatrix.sync.aligned.m8n8.x4.shared.b16 {%0,%1,%2,%3}, [%4];"
                 : "=r"(r[0]), "=r"(r[1]), "=r"(r[2]), "=r"(r[3]) : "r"(addr));
}
__device__ __forceinline__ void ldx4t(uint32_t* r, uint32_t addr) {
    asm volatile("ldmatrix.sync.aligned.m8n8.x4.trans.shared.b16 {%0,%1,%2,%3}, [%4];"
                 : "=r"(r[0]), "=r"(r[1]), "=r"(r[2]), "=r"(r[3]) : "r"(addr));
}
__device__ __forceinline__ void mma16816(float* c, const uint32_t* a,
                                         uint32_t b0, uint32_t b1) {
    asm volatile(
        "mma.sync.aligned.m16n8k16.row.col.f32.f16.f16.f32 "
        "{%0,%1,%2,%3}, {%4,%5,%6,%7}, {%8,%9}, {%0,%1,%2,%3};"
        : "+f"(c[0]), "+f"(c[1]), "+f"(c[2]), "+f"(c[3])
        : "r"(a[0]), "r"(a[1]), "r"(a[2]), "r"(a[3]), "r"(b0), "r"(b1));
}
__device__ __forceinline__ void cpa16(uint32_t dst, const void* src) {
    asm volatile("cp.async.cg.shared.global [%0], [%1], 16;"
                 :: "r"(dst), "l"(src) : "memory");
}
__device__ __forceinline__ void split_store(__half* hi, __half* lo, size_t idx,
                                            float x0, float x1) {
    __half h0 = __float2half_rn(x0), h1 = __float2half_rn(x1);
    __half2 hh = __halves2half2(h0, h1);
    __half2 llv = __floats2half2_rn(x0 - __half2float(h0), x1 - __half2float(h1));
    *(uint32_t*)(hi + idx) = *(uint32_t*)&hh;
    *(uint32_t*)(lo + idx) = *(uint32_t*)&llv;
}
__device__ __forceinline__ void sts_cvt(uint32_t dst, float4 u0, float4 u1) {
    __half2 a = __floats2half2_rn(u0.x, u0.y);
    __half2 b = __floats2half2_rn(u0.z, u0.w);
    __half2 c = __floats2half2_rn(u1.x, u1.y);
    __half2 d = __floats2half2_rn(u1.z, u1.w);
    asm volatile("st.shared.v4.b32 [%0], {%1,%2,%3,%4};"
                 :: "r"(dst), "r"(*(uint32_t*)&a), "r"(*(uint32_t*)&b),
                    "r"(*(uint32_t*)&c), "r"(*(uint32_t*)&d) : "memory");
}

// -------- fused fp32 -> fp16 convert: x, wq, wk, wv (grid-stride) ----------
__global__ void cvt_all(const float* __restrict__ x,  const float* __restrict__ wq,
                        const float* __restrict__ wk, const float* __restrict__ wv,
                        __half* __restrict__ xh,  __half* __restrict__ wqh,
                        __half* __restrict__ wkh, __half* __restrict__ wvh)
{
    const long NB = (long)MM * DIMS / 4;    // 4M float4
    const long NK = (long)DKV * DIMS / 4;   // 1M float4
    const long total = 2 * NB + 2 * NK;
    const long stride = (long)gridDim.x * blockDim.x;
    for (long i = (long)blockIdx.x * blockDim.x + threadIdx.x; i < total; i += stride) {
        const float* in; __half* out; long j = i;
        if (j < NB)               { in = x;  out = xh; }
        else if (j < 2 * NB)      { in = wq; out = wqh; j -= NB; }
        else if (j < 2 * NB + NK) { in = wk; out = wkh; j -= 2 * NB; }
        else                      { in = wv; out = wvh; j -= 2 * NB + NK; }
        float4 v = ((const float4*)in)[j];
        __half2 h0 = __floats2half2_rn(v.x, v.y);
        __half2 h1 = __floats2half2_rn(v.z, v.w);
        ((uint2*)out)[j] = make_uint2(*(uint32_t*)&h0, *(uint32_t*)&h1);
    }
}

// ============ shared GEMM mainloop constants (GTK=64, 3-stage) =============
#define GTK 64
#define HROW 144                     // 128B data + 16B pad per row
#define HTILE_B (128 * HROW)         // 18432 per operand
#define STAGE_B (2 * HTILE_B)        // 36864
#define NSTAGE  3
#define GEMM_SMEM (NSTAGE * STAGE_B) // 110592 -> 2 CTAs/SM

// fp16 B mainloop (gemm_qkv) — unchanged from round 14
#define GEMM_MAINLOOP(A_, B_, K_)                                              \
    const __half* aSrc[4]; const __half* bSrc[4]; uint32_t dOff[4];            \
    _Pragma("unroll")                                                          \
    for (int j = 0; j < 4; j++) {                                              \
        int idx = tid + j * 256;                                               \
        int r = idx >> 3, c = idx & 7;                                         \
        aSrc[j] = A_ + (size_t)(bm + r) * K_ + c * 8;                          \
        bSrc[j] = B_ + (size_t)(bnl + r) * K_ + c * 8;                         \
        dOff[j] = r * HROW + c * 16;                                           \
    }                                                                          \
    const uint32_t aOff = (uint32_t)(wm * 32 + (lsel & 1) * 8 + lrow) * HROW   \
                        + (uint32_t)(lsel >> 1) * 16;                          \
    const uint32_t bOff = (uint32_t)(wn * 64 + (lsel >> 1) * 8 + lrow) * HROW  \
                        + (uint32_t)(lsel & 1) * 16;                           \
    float acc[2][8][4];                                                        \
    _Pragma("unroll")                                                          \
    for (int mt = 0; mt < 2; mt++)                                             \
        _Pragma("unroll")                                                      \
        for (int nt = 0; nt < 8; nt++)                                         \
            _Pragma("unroll")                                                  \
            for (int i = 0; i < 4; i++) acc[mt][nt][i] = 0.0f;                 \
    const int KT = K_ / GTK;                                                   \
    _Pragma("unroll")                                                          \
    for (int st = 0; st < NSTAGE - 1; st++) {                                  \
        const uint32_t sb = smb + st * STAGE_B;                                \
        const size_t ko = (size_t)st * GTK;                                    \
        _Pragma("unroll")                                                      \
        for (int j = 0; j < 4; j++) {                                          \
            cpa16(sb + dOff[j], aSrc[j] + ko);                                 \
            cpa16(sb + HTILE_B + dOff[j], bSrc[j] + ko);                       \
        }                                                                      \
        asm volatile("cp.async.commit_group;" ::: "memory");                   \
    }                                                                          \
    int cb = 0, pb = NSTAGE - 1;                                               \
    for (int kt = 0; kt < KT; kt++) {                                          \
        asm volatile("cp.async.wait_group %0;" :: "n"(NSTAGE - 2) : "memory"); \
        __syncthreads();                                                       \
        const uint32_t bufA = smb + cb * STAGE_B;                              \
        const uint32_t bufB = bufA + HTILE_B;                                  \
        if (++cb == NSTAGE) cb = 0;                                            \
        _Pragma("unroll")                                                      \
        for (int ks = 0; ks < 4; ks++) {                                       \
            uint32_t a[2][4], b[4][4];                                         \
            _Pragma("unroll")                                                  \
            for (int mt = 0; mt < 2; mt++)                                     \
                ldx4(a[mt], bufA + aOff + mt * (16 * HROW) + ks * 32);         \
            _Pragma("unroll")                                                  \
            for (int p = 0; p < 4; p++)                                        \
                ldx4(b[p], bufB + bOff + p * (16 * HROW) + ks * 32);           \
            _Pragma("unroll")                                                  \
            for (int mt = 0; mt < 2; mt++)                                     \
                _Pragma("unroll")                                              \
                for (int nt = 0; nt < 8; nt++)                                 \
                    mma16816(acc[mt][nt], a[mt],                               \
                             b[nt >> 1][(nt & 1) * 2], b[nt >> 1][(nt & 1) * 2 + 1]); \
            if (ks == 0) {                                                     \
                const int kp = (kt + NSTAGE - 1 < KT) ? (kt + NSTAGE - 1) : (KT - 1); \
                const uint32_t sb = smb + pb * STAGE_B;                        \
                const size_t ko = (size_t)kp * GTK;                            \
                _Pragma("unroll")                                              \
                for (int j = 0; j < 4; j++) {                                  \
                    cpa16(sb + dOff[j], aSrc[j] + ko);                         \
                    cpa16(sb + HTILE_B + dOff[j], bSrc[j] + ko);               \
                }                                                              \
                asm volatile("cp.async.commit_group;" ::: "memory");           \
                if (++pb == NSTAGE) pb = 0;                                    \
            }                                                                  \
        }                                                                      \
    }

// ======== Fused QKV projection GEMM + RoPE + hi/lo split epilogue ==========
__global__ __launch_bounds__(256, 2) void gemm_qkv(const __half* __restrict__ A,
                                                   const __half* __restrict__ WQ,
                                                   const __half* __restrict__ WK,
                                                   const __half* __restrict__ WV,
                                                   __half* __restrict__ qhi, __half* __restrict__ qlo,
                                                   __half* __restrict__ khi, __half* __restrict__ klo,
                                                   __half* __restrict__ vhi, __half* __restrict__ vlo,
                                                   const float* __restrict__ freqs)
{
    extern __shared__ char sm[];
    const uint32_t smb = smem_u32(sm);
    const int tid  = threadIdx.x;
    const int lane = tid & 31;
    const int warp = tid >> 5;
    const int wm   = warp >> 1;
    const int wn   = warp & 1;
    const int lq   = lane >> 2;
    const int lt   = lane & 3;
    const int lrow = lane & 7;
    const int lsel = lane >> 3;

    const int bx = blockIdx.x;
    int mode; const __half* Bm; int bnl;
    if (bx < 32)      { mode = 0; Bm = WQ; bnl = bx * 128; }
    else if (bx < 40) { mode = 1; Bm = WK; bnl = (bx - 32) * 128; }
    else              { mode = 2; Bm = WV; bnl = (bx - 40) * 128; }
    const int bm = blockIdx.y * 128;

    GEMM_MAINLOOP(A, Bm, DIMS)

    const float qscale = 0.088388347648318447f;   // 1/sqrt(128)
    const int nh  = (mode == 0) ? NH : NKV;
    __half* hiB = (mode == 0) ? qhi : (mode == 1) ? khi : vhi;
    __half* loB = (mode == 0) ? qlo : (mode == 1) ? klo : vlo;
    const float scl = (mode == 0) ? qscale : 1.0f;

#pragma unroll
    for (int mt = 0; mt < 2; mt++) {
        const int r0 = bm + wm * 32 + mt * 16 + lq;
#pragma unroll
        for (int nt = 0; nt < 8; nt++) {
            const int c  = bnl + wn * 64 + nt * 8 + 2 * lt;   // even
            const int h  = c >> 7;
            const int d  = c & 127;
            if (mode == 2) {
#pragma unroll
                for (int rr = 0; rr < 2; rr++) {
                    const int r = r0 + rr * 8;
                    const int l = r & (LL - 1), bq = r >> 10;
                    size_t idx = (((size_t)(bq * nh + h) * LL + l) * HD + d);
                    split_store(hiB, loB, idx, acc[mt][nt][rr * 2], acc[mt][nt][rr * 2 + 1]);
                }
            } else {
                const int d2 = d >> 1;
#pragma unroll
                for (int rr = 0; rr < 2; rr++) {
                    const int r = r0 + rr * 8;
                    const int l = r & (LL - 1), bq = r >> 10;
                    const float f = freqs[l * 64 + d2];
                    const float cs = cosf(f), sn = sinf(f);
                    const float a0 = acc[mt][nt][rr * 2], a1 = acc[mt][nt][rr * 2 + 1];
                    const float x0 = (a0 * cs - a1 * sn) * scl;
                    const float x1 = (a0 * sn + a1 * cs) * scl;
                    size_t idx = (((size_t)(bq * nh + h) * LL + l) * HD + d);
                    split_store(hiB, loB, idx, x0, x1);
                }
            }
        }
    }
}

// ==== wo GEMM: A fp16, B fp32 (wo) with fused cvt in the B producer ========
#define KSBATCH(ks_)                                                           \
    {                                                                          \
        uint32_t a[2][4], b[4][4];                                             \
        _Pragma("unroll")                                                      \
        for (int mt = 0; mt < 2; mt++)                                         \
            ldx4(a[mt], bufA + aOff + mt * (16 * HROW) + (ks_) * 32);          \
        _Pragma("unroll")                                                      \
        for (int p = 0; p < 4; p++)                                            \
            ldx4(b[p], bufB + bOff + p * (16 * HROW) + (ks_) * 32);            \
        _Pragma("unroll")                                                      \
        for (int mt = 0; mt < 2; mt++)                                         \
            _Pragma("unroll")                                                  \
            for (int nt = 0; nt < 8; nt++)                                     \
                mma16816(acc[mt][nt], a[mt],                                   \
                         b[nt >> 1][(nt & 1) * 2], b[nt >> 1][(nt & 1) * 2 + 1]); \
    }

__global__ __launch_bounds__(256, 2) void gemm_h(const __half* __restrict__ A,
                                                 const float* __restrict__ Bw,
                                                 float* __restrict__ C,
                                                 int N, int K)
{
    extern __shared__ char sm[];
    const uint32_t smb = smem_u32(sm);
    const int tid  = threadIdx.x;
    const int lane = tid & 31;
    const int warp = tid >> 5;
    const int wm   = warp >> 1;
    const int wn   = warp & 1;
    const int lq   = lane >> 2;
    const int lt   = lane & 3;
    const int lrow = lane & 7;
    const int lsel = lane >> 3;
    const int bm  = blockIdx.y * 128;
    const int bnl = blockIdx.x * 128;

    const __half* aSrc[4]; const float* bSrc[4]; uint32_t dOff[4];
#pragma unroll
    for (int j = 0; j < 4; j++) {
        int idx = tid + j * 256;
        int r = idx >> 3, c = idx & 7;
        aSrc[j] = A  + (size_t)(bm + r) * K + c * 8;
        bSrc[j] = Bw + (size_t)(bnl + r) * K + c * 8;
        dOff[j] = r * HROW + c * 16;
    }
    const uint32_t aOff = (uint32_t)(wm * 32 + (lsel & 1) * 8 + lrow) * HROW
                        + (uint32_t)(lsel >> 1) * 16;
    const uint32_t bOff = (uint32_t)(wn * 64 + (lsel >> 1) * 8 + lrow) * HROW
                        + (uint32_t)(lsel & 1) * 16;

    float acc[2][8][4];
#pragma unroll
    for (int mt = 0; mt < 2; mt++)
#pragma unroll
        for (int nt = 0; nt < 8; nt++)
#pragma unroll
            for (int i = 0; i < 4; i++) acc[mt][nt][i] = 0.0f;

    const int KT = K / GTK;

    // Prologue: A via cp.async (stages 0,1); B via direct LDG->cvt->STS.
#pragma unroll
    for (int st = 0; st < NSTAGE - 1; st++) {
        const uint32_t sb = smb + st * STAGE_B;
        const size_t ko = (size_t)st * GTK;
#pragma unroll
        for (int j = 0; j < 4; j++)
            cpa16(sb + dOff[j], aSrc[j] + ko);
        asm volatile("cp.async.commit_group;" ::: "memory");
#pragma unroll
        for (int j = 0; j < 4; j++) {
            float4 u0 = *(const float4*)(bSrc[j] + ko);
            float4 u1 = *(const float4*)(bSrc[j] + ko + 4);
            sts_cvt(sb + HTILE_B + dOff[j], u0, u1);
        }
    }

    int cb = 0, pb = NSTAGE - 1;
    for (int kt = 0; kt < KT; kt++) {
        asm volatile("cp.async.wait_group %0;" :: "n"(NSTAGE - 2) : "memory");
        __syncthreads();
        const uint32_t bufA = smb + cb * STAGE_B;
        const uint32_t bufB = bufA + HTILE_B;
        if (++cb == NSTAGE) cb = 0;

        const int kp = (kt + NSTAGE - 1 < KT) ? (kt + NSTAGE - 1) : (KT - 1);
        const uint32_t sb = smb + pb * STAGE_B;
        const size_t ko = (size_t)kp * GTK;
        if (++pb == NSTAGE) pb = 0;

        float4 u[4][2];
        KSBATCH(0)
        // A prefetch + first half of B LDG, overlapped with busy tensor pipe
#pragma unroll
        for (int j = 0; j < 4; j++)
            cpa16(sb + dOff[j], aSrc[j] + ko);
        asm volatile("cp.async.commit_group;" ::: "memory");
        u[0][0] = *(const float4*)(bSrc[0] + ko);
        u[0][1] = *(const float4*)(bSrc[0] + ko + 4);
        u[1][0] = *(const float4*)(bSrc[1] + ko);
        u[1][1] = *(const float4*)(bSrc[1] + ko + 4);
        KSBATCH(1)
        u[2][0] = *(const float4*)(bSrc[2] + ko);
        u[2][1] = *(const float4*)(bSrc[2] + ko + 4);
        u[3][0] = *(const float4*)(bSrc[3] + ko);
        u[3][1] = *(const float4*)(bSrc[3] + ko + 4);
        KSBATCH(2)
        sts_cvt(sb + HTILE_B + dOff[0], u[0][0], u[0][1]);
        sts_cvt(sb + HTILE_B + dOff[1], u[1][0], u[1][1]);
        KSBATCH(3)
        sts_cvt(sb + HTILE_B + dOff[2], u[2][0], u[2][1]);
        sts_cvt(sb + HTILE_B + dOff[3], u[3][0], u[3][1]);
    }

#pragma unroll
    for (int mt = 0; mt < 2; mt++) {
        int r0 = bm + wm * 32 + mt * 16 + lq;
#pragma unroll
        for (int nt = 0; nt < 8; nt++) {
            int c = bnl + wn * 64 + nt * 8 + 2 * lt;
            *(float2*)(C + (size_t)r0 * N + c)       = make_float2(acc[mt][nt][0], acc[mt][nt][1]);
            *(float2*)(C + (size_t)(r0 + 8) * N + c) = make_float2(acc[mt][nt][2], acc[mt][nt][3]);
        }
    }
}

// ======== MMA flash attention: pre-split fp16, 64-row Q tiles ==============
// S = QhKh + QhKl + QlKh (3-term) ; O += PhVh + PhVl (2-term: Plo dropped —
// P errors are not exp-amplified; adds ~2e-4 relative, see analysis).
#define PIT   272
#define AQHI  0
#define AQLO  17408
#define AKHI  34816
#define AKLO  52224
#define AVHI  69632
#define AVLO  87040
#define ATTN_SMEM 104448   // x2 CTAs = 208896 <= 228KB/SM

__global__ __launch_bounds__(128, 2) void attn_mma(const __half* __restrict__ qhi,
                                                   const __half* __restrict__ qlo,
                                                   const __half* __restrict__ khi,
                                                   const __half* __restrict__ klo,
                                                   const __half* __restrict__ vhi,
                                                   const __half* __restrict__ vlo,
                                                   __half* __restrict__ o)
{
    extern __shared__ char smx[];
    const uint32_t smb = smem_u32(smx);
    const int tid = threadIdx.x, lane = tid & 31, w = tid >> 5;
    const int lq = lane >> 2, lt = lane & 3, lrow = lane & 7, lsel = lane >> 3;
    const int qt = (gridDim.x - 1) - blockIdx.x;   // heavy tiles first
    const int h = blockIdx.y, b = blockIdx.z;
    const int qbase = qt * 64;
    const int kvh = h >> 2;

    const __half* qhg = qhi + (((size_t)(b * NH + h) * LL + qbase) * HD);
    const __half* qlg = qlo + (((size_t)(b * NH + h) * LL + qbase) * HD);
#pragma unroll
    for (int j = 0; j < 16; j++) {
        int idx = tid + j * 128;
        int arr = idx >> 10;
        int e = idx & 1023;
        int r = e >> 4, c = e & 15;
        const __half* src = (arr ? qlg : qhg) + (size_t)r * HD + c * 8;
        cpa16(smb + (arr ? AQLO : AQHI) + r * PIT + c * 16, src);
    }
    asm volatile("cp.async.commit_group;" ::: "memory");

    float oacc[16][4];
#pragma unroll
    for (int j = 0; j < 16; j++)
#pragma unroll
        for (int i = 0; i < 4; i++) oacc[j][i] = 0.0f;
    float m0 = -1e30f, m1 = -1e30f, l0 = 0.0f, l1 = 0.0f;

    const __half* khg = khi + ((size_t)(b * NKV + kvh) * LL) * HD;
    const __half* klg = klo + ((size_t)(b * NKV + kvh) * LL) * HD;
    const __half* vhg = vhi + ((size_t)(b * NKV + kvh) * LL) * HD;
    const __half* vlg = vlo + ((size_t)(b * NKV + kvh) * LL) * HD;

    const uint32_t qOff = (uint32_t)(w * 16 + (lsel & 1) * 8 + lrow) * PIT
                        + (uint32_t)(lsel >> 1) * 16;
    const uint32_t kOff = (uint32_t)((lsel >> 1) * 8 + lrow) * PIT
                        + (uint32_t)(lsel & 1) * 16;
    const uint32_t vRow = (uint32_t)((lsel & 1) * 8 + lrow) * PIT
                        + (uint32_t)(lsel >> 1) * 16;

    for (int kt = 0; kt <= qt; kt++) {
        __syncthreads();
        // K tile: own commit group
#pragma unroll
        for (int j = 0; j < 16; j++) {
            int idx = tid + j * 128;
            int arr = idx >> 10;
            int e = idx & 1023;
            int r = e >> 4, c = e & 15;
            size_t go = (size_t)(kt * 64 + r) * HD + c * 8;
            cpa16(smb + (arr ? AKLO : AKHI) + r * PIT + c * 16,
                  (arr ? klg : khg) + go);
        }
        asm volatile("cp.async.commit_group;" ::: "memory");
        // V tile: separate group, in flight during S
#pragma unroll
        for (int j = 0; j < 16; j++) {
            int idx = tid + j * 128;
            int arr = idx >> 10;
            int e = idx & 1023;
            int r = e >> 4, c = e & 15;
            size_t go = (size_t)(kt * 64 + r) * HD + c * 8;
            cpa16(smb + (arr ? AVLO : AVHI) + r * PIT + c * 16,
                  (arr ? vlg : vhg) + go);
        }
        asm volatile("cp.async.commit_group;" ::: "memory");
        asm volatile("cp.async.wait_group 1;" ::: "memory");   // Q+K ready
        __syncthreads();

        float sacc[8][4];
#pragma unroll
        for (int nt = 0; nt < 8; nt++)
#pragma unroll
            for (int i = 0; i < 4; i++) sacc[nt][i] = 0.0f;

#pragma unroll
        for (int c = 0; c < 8; c++) {
            uint32_t qh[4], ql[4];
            ldx4(qh, smb + AQHI + qOff + c * 32);
            ldx4(ql, smb + AQLO + qOff + c * 32);
#pragma unroll
            for (int p = 0; p < 4; p++) {
                uint32_t kh[4], kl[4];
                ldx4(kh, smb + AKHI + kOff + p * (16 * PIT) + c * 32);
                ldx4(kl, smb + AKLO + kOff + p * (16 * PIT) + c * 32);
                mma16816(sacc[2 * p],     qh, kh[0], kh[1]);
                mma16816(sacc[2 * p],     qh, kl[0], kl[1]);
                mma16816(sacc[2 * p],     ql, kh[0], kh[1]);
                mma16816(sacc[2 * p + 1], qh, kh[2], kh[3]);
                mma16816(sacc[2 * p + 1], qh, kl[2], kl[3]);
                mma16816(sacc[2 * p + 1], ql, kh[2], kh[3]);
            }
        }

        if (kt == qt) {
            const int qg0 = qbase + w * 16 + lq;
            const int qg1 = qg0 + 8;
            const int kvb = kt * 64;
#pragma unroll
            for (int nt = 0; nt < 8; nt++) {
                int cv = kvb + nt * 8 + 2 * lt;
                if (cv     > qg0) sacc[nt][0] = -1e30f;
                if (cv + 1 > qg0) sacc[nt][1] = -1e30f;
                if (cv     > qg1) sacc[nt][2] = -1e30f;
                if (cv + 1 > qg1) sacc[nt][3] = -1e30f;
            }
        }

        float mx0 = -1e30f, mx1 = -1e30f;
#pragma unroll
        for (int nt = 0; nt < 8; nt++) {
            mx0 = fmaxf(mx0, fmaxf(sacc[nt][0], sacc[nt][1]));
            mx1 = fmaxf(mx1, fmaxf(sacc[nt][2], sacc[nt][3]));
        }
        mx0 = fmaxf(mx0, __shfl_xor_sync(0xffffffffu, mx0, 1));
        mx0 = fmaxf(mx0, __shfl_xor_sync(0xffffffffu, mx0, 2));
        mx1 = fmaxf(mx1, __shfl_xor_sync(0xffffffffu, mx1, 1));
        mx1 = fmaxf(mx1, __shfl_xor_sync(0xffffffffu, mx1, 2));
        float mn0 = fmaxf(m0, mx0), mn1 = fmaxf(m1, mx1);
        float cr0 = __expf(m0 - mn0), cr1 = __expf(m1 - mn1);
        m0 = mn0; m1 = mn1;
        float sum0 = 0.0f, sum1 = 0.0f;
#pragma unroll
        for (int nt = 0; nt < 8; nt++) {
            sacc[nt][0] = __expf(sacc[nt][0] - m0); sum0 += sacc[nt][0];
            sacc[nt][1] = __expf(sacc[nt][1] - m0); sum0 += sacc[nt][1];
            sacc[nt][2] = __expf(sacc[nt][2] - m1); sum1 += sacc[nt][2];
            sacc[nt][3] = __expf(sacc[nt][3] - m1); sum1 += sacc[nt][3];
        }
        sum0 += __shfl_xor_sync(0xffffffffu, sum0, 1);
        sum0 += __shfl_xor_sync(0xffffffffu, sum0, 2);
        sum1 += __shfl_xor_sync(0xffffffffu, sum1, 1);
        sum1 += __shfl_xor_sync(0xffffffffu, sum1, 2);
        l0 = l0 * cr0 + sum0;
        l1 = l1 * cr1 + sum1;
#pragma unroll
        for (int j = 0; j < 16; j++) {
            oacc[j][0] *= cr0; oacc[j][1] *= cr0;
            oacc[j][2] *= cr1; oacc[j][3] *= cr1;
        }

        asm volatile("cp.async.wait_group 0;" ::: "memory");   // V ready
        __syncthreads();

        // O += P V  (2-term: PhVh + PhVl)
#pragma unroll
        for (int c = 0; c < 4; c++) {
            uint32_t phi[4];
#pragma unroll
            for (int u = 0; u < 4; u++) {
                float pa = sacc[2 * c + (u >> 1)][(u & 1) * 2];
                float pb = sacc[2 * c + (u >> 1)][(u & 1) * 2 + 1];
                __half2 hh = __floats2half2_rn(pa, pb);
                phi[u] = *(uint32_t*)&hh;
            }
#pragma unroll
            for (int jp = 0; jp < 8; jp++) {
                uint32_t vh[4], vl[4];
                uint32_t va = smb + vRow + c * (16 * PIT) + jp * 32;
                ldx4t(vh, va + AVHI);
                ldx4t(vl, va + AVLO);
                mma16816(oacc[2 * jp],     phi, vh[0], vh[1]);
                mma16816(oacc[2 * jp],     phi, vl[0], vl[1]);
                mma16816(oacc[2 * jp + 1], phi, vh[2], vh[3]);
                mma16816(oacc[2 * jp + 1], phi, vl[2], vl[3]);
            }
        }
    }

    const float i0 = 1.0f / l0, i1 = 1.0f / l1;
    const int row0 = qbase + w * 16 + lq;
    __half* ob0 = o + (size_t)(b * LL + row0) * DIMS + h * HD;
    __half* ob1 = ob0 + (size_t)8 * DIMS;
#pragma unroll
    for (int j = 0; j < 16; j++) {
        int col = j * 8 + 2 * lt;
        __half2 h0 = __floats2half2_rn(oacc[j][0] * i0, oacc[j][1] * i0);
        __half2 h1 = __floats2half2_rn(oacc[j][2] * i1, oacc[j][3] * i1);
        *(uint32_t*)(ob0 + col) = *(uint32_t*)&h0;
        *(uint32_t*)(ob1 + col) = *(uint32_t*)&h1;
    }
}

// ---------------------------------------------------------------------------
extern "C" void kernel_launch(void* const* d_in, const int* in_sizes, int n_in,
                              void* d_out, int out_size)
{
    const float* x  = (const float*)d_in[0];
    const float* wq = (const float*)d_in[1];
    const float* wk = (const float*)d_in[2];
    const float* wv = (const float*)d_in[3];
    const float* wo = (const float*)d_in[4];
    const float* fr = (const float*)d_in[5];
    float* out = (float*)d_out;

    __half *xh, *wqh, *wkh, *wvh, *ah;
    __half *qhi, *qlo, *khi, *klo, *vhi, *vlo;
    cudaGetSymbolAddress((void**)&xh,  g_xh);
    cudaGetSymbolAddress((void**)&wqh, g_wqh);
    cudaGetSymbolAddress((void**)&wkh, g_wkh);
    cudaGetSymbolAddress((void**)&wvh, g_wvh);
    cudaGetSymbolAddress((void**)&ah,  g_ah);
    cudaGetSymbolAddress((void**)&qhi, g_qhi);
    cudaGetSymbolAddress((void**)&qlo, g_qlo);
    cudaGetSymbolAddress((void**)&khi, g_khi);
    cudaGetSymbolAddress((void**)&klo, g_klo);
    cudaGetSymbolAddress((void**)&vhi, g_vhi);
    cudaGetSymbolAddress((void**)&vlo, g_vlo);

    cudaFuncSetAttribute(gemm_qkv, cudaFuncAttributeMaxDynamicSharedMemorySize, GEMM_SMEM);
    cudaFuncSetAttribute(gemm_h,   cudaFuncAttributeMaxDynamicSharedMemorySize, GEMM_SMEM);
    cudaFuncSetAttribute(attn_mma, cudaFuncAttributeMaxDynamicSharedMemorySize, ATTN_SMEM);

    // fp32->fp16 for x + QKV weights (wo is converted inside gemm_h)
    cvt_all<<<2048, 256>>>(x, wq, wk, wv, xh, wqh, wkh, wvh);

    gemm_qkv<<<dim3(48, MM / 128), 256, GEMM_SMEM>>>(
        xh, wqh, wkh, wvh, qhi, qlo, khi, klo, vhi, vlo, fr);

    attn_mma<<<dim3(LL / 64, NH, BB), 128, ATTN_SMEM>>>(qhi, qlo, khi, klo, vhi, vlo, ah);

    gemm_h<<<dim3(DIMS / 128, MM / 128), 256, GEMM_SMEM>>>(ah, wo, out, DIMS, DIMS);
}